// round 4
// baseline (speedup 1.0000x reference)
#include <cuda_runtime.h>
#include <cuda_bf16.h>
#include <cstdint>

typedef unsigned long long ULL;

// ---------------- scratch (static device globals; no allocation) ------------
__device__ float g_X0[524288 * 68];      // layer0 input [feat64 | xyz3 | pad]
__device__ float g_y0[524288 * 64];      // raw layer0 out
__device__ float g_y1[524288 * 64];      // raw layer1 out
__device__ float g_y2[(size_t)524288 * 128]; // raw layer2 out
__device__ float g_maxraw[16384 * 128];  // max over K of raw y2
__device__ int   g_fpsidx[8 * 2048];
__device__ float g_cent[16384 * 3];
__device__ int   g_gidx[524288];
__device__ float g_Wt0[68 * 64];
__device__ float g_Wt1[64 * 64];
__device__ float g_Wt2[64 * 128];
__device__ float g_s0[64], g_q0[64], g_s1[64], g_q1[64], g_s2[128], g_q2[128];
__device__ float g_a0[64], g_c0[64], g_a1[64], g_c1[64], g_a2[128], g_c2[128];

// ---------------- helpers ---------------------------------------------------
__device__ __forceinline__ ULL packf2(float lo, float hi) {
    ULL r; unsigned a = __float_as_uint(lo), b = __float_as_uint(hi);
    asm("mov.b64 %0,{%1,%2};" : "=l"(r) : "r"(a), "r"(b)); return r;
}
__device__ __forceinline__ float2 unpackf2(ULL v) {
    unsigned a, b; asm("mov.b64 {%0,%1},%2;" : "=r"(a), "=r"(b) : "l"(v));
    return make_float2(__uint_as_float(a), __uint_as_float(b));
}
__device__ __forceinline__ ULL f2add(ULL a, ULL b) {
    ULL r; asm("add.rn.f32x2 %0,%1,%2;" : "=l"(r) : "l"(a), "l"(b)); return r;
}
__device__ __forceinline__ ULL f2mul(ULL a, ULL b) {
    ULL r; asm("mul.rn.f32x2 %0,%1,%2;" : "=l"(r) : "l"(a), "l"(b)); return r;
}
__device__ __forceinline__ float d2_noFMA(float dx, float dy, float dz) {
    return __fadd_rn(__fadd_rn(__fmul_rn(dx, dx), __fmul_rn(dy, dy)), __fmul_rn(dz, dz));
}

// ---------------- zero stats -------------------------------------------------
__global__ void zero_k() {
    int t = threadIdx.x;
    if (t < 64) { g_s0[t]=0.f; g_q0[t]=0.f; g_s1[t]=0.f; g_q1[t]=0.f; }
    if (t < 128){ g_s2[t]=0.f; g_q2[t]=0.f; }
}

// ---------------- FPS: 1 CTA/batch, 512 thr, 16 pts/thread ------------------
__global__ void __launch_bounds__(512) fps_k(const float* __restrict__ xyz) {
    __shared__ unsigned swmax[16];
    __shared__ unsigned s_arg, s_max;
    const int b = blockIdx.x, tid = threadIdx.x, wid = tid >> 5, lane = tid & 31;
    const float* X = xyz + (size_t)b * 24576;

    ULL px[8], py[8], pz[8]; float dist[16];
#pragma unroll
    for (int j = 0; j < 8; j++) {
        int p0 = tid + 1024 * j, p1 = p0 + 512;
        px[j] = packf2(X[3*p0+0], X[3*p1+0]);
        py[j] = packf2(X[3*p0+1], X[3*p1+1]);
        pz[j] = packf2(X[3*p0+2], X[3*p1+2]);
        dist[2*j] = 1e10f; dist[2*j+1] = 1e10f;
    }
    float cx = X[0], cy = X[1], cz = X[2];
    if (tid == 0) g_fpsidx[b * 2048] = 0;

    for (int s = 1; s < 2048; s++) {
        ULL ncx = packf2(-cx, -cx), ncy = packf2(-cy, -cy), ncz = packf2(-cz, -cz);
        float m8 = 0.0f;
#pragma unroll
        for (int j = 0; j < 8; j++) {
            ULL dx = f2add(px[j], ncx);
            ULL dy = f2add(py[j], ncy);
            ULL dz = f2add(pz[j], ncz);
            // mul/add tree, no FMA: matches reference rounding exactly
            ULL d2 = f2add(f2add(f2mul(dx, dx), f2mul(dy, dy)), f2mul(dz, dz));
            float2 d = unpackf2(d2);
            float a = fminf(dist[2*j],   d.x); dist[2*j]   = a;
            float c = fminf(dist[2*j+1], d.y); dist[2*j+1] = c;
            m8 = fmaxf(m8, fmaxf(a, c));
        }
        unsigned mb = __float_as_uint(m8);                 // dists >= 0: bit-monotone
        unsigned wm = __reduce_max_sync(0xffffffffu, mb);
        if (lane == 0) swmax[wid] = wm;
        __syncthreads();
        if (wid == 0) {
            unsigned v = (lane < 16) ? swmax[lane] : 0u;
            v = __reduce_max_sync(0xffffffffu, v);
            if (lane == 0) s_max = v;
        }
        if (tid == 0) s_arg = 0xffffffffu;
        __syncthreads();
        unsigned gm = s_max;
        if (mb == gm) {
#pragma unroll
            for (int i = 0; i < 16; i++) {
                if (__float_as_uint(dist[i]) == gm) {      // first (lowest index) match
                    atomicMin(&s_arg, (unsigned)(tid + (i << 9)));
                    break;
                }
            }
        }
        __syncthreads();
        unsigned p = s_arg;
        if (tid == 0) g_fpsidx[b * 2048 + s] = (int)p;
        cx = X[3*p]; cy = X[3*p+1]; cz = X[3*p+2];
    }
}

// ---------------- centroids --------------------------------------------------
__global__ void centroid_k(const float* __restrict__ xyz, float* __restrict__ outc) {
    int id = blockIdx.x * 256 + threadIdx.x;          // 0..16383
    if (id >= 16384) return;
    int b = id >> 11;
    int p = g_fpsidx[id];
    const float* src = xyz + ((size_t)(b << 13) + p) * 3;
    float x = src[0], y = src[1], z = src[2];
    outc[id*3+0] = x; outc[id*3+1] = y; outc[id*3+2] = z;
    g_cent[id*3+0] = x; g_cent[id*3+1] = y; g_cent[id*3+2] = z;
}

// ---------------- ball query: warp per centroid ------------------------------
__global__ void __launch_bounds__(256) ballq_k(const float* __restrict__ xyz) {
    __shared__ int sidx[8][32];
    int wid = threadIdx.x >> 5, lane = threadIdx.x & 31;
    int cid = blockIdx.x * 8 + wid;                   // 0..16383
    int b = cid >> 11;
    float cx = g_cent[cid*3], cy = g_cent[cid*3+1], cz = g_cent[cid*3+2];
    const float* X = xyz + (size_t)b * 24576;

    int cnt = 0;
    for (int base = 0; base < 8192; base += 32) {
        int j = base + lane;
        float d2 = d2_noFMA(cx - X[3*j], cy - X[3*j+1], cz - X[3*j+2]);
        bool hit = d2 <= 0.04f;
        unsigned m = __ballot_sync(0xffffffffu, hit);
        if (m) {
            int r = __popc(m & ((1u << lane) - 1u));
            if (hit && cnt + r < 32) sidx[wid][cnt + r] = j;
            cnt += __popc(m);
            if (cnt >= 32) break;
        }
    }
    __syncwarp();
    int first = sidx[wid][0];                          // >=1 hit always (centroid itself)
    int c = cnt < 32 ? cnt : 32;
    g_gidx[cid * 32 + lane] = (lane < c) ? sidx[wid][lane] : first;
}

// ---------------- weight transpose (k-major) ---------------------------------
__global__ void prepw_k(const float* __restrict__ w0, const float* __restrict__ w1,
                        const float* __restrict__ w2) {
    int t = blockIdx.x * 256 + threadIdx.x;
    if (t < 68 * 64) {
        int k = t >> 6, n = t & 63;
        float v = 0.f;
        if (k < 64) v = w0[n * 67 + 3 + k];            // X0 layout: feats first
        else if (k < 67) v = w0[n * 67 + (k - 64)];    // then xyz
        g_Wt0[k * 64 + n] = v;
    }
    int t1 = t - 68 * 64;
    if (t1 >= 0 && t1 < 64 * 64) {
        int k = t1 >> 6, n = t1 & 63;
        g_Wt1[k * 64 + n] = w1[n * 64 + k];
    }
    int t2 = t1 - 64 * 64;
    if (t2 >= 0 && t2 < 64 * 128) {
        int k = t2 >> 7, n = t2 & 127;
        g_Wt2[k * 128 + n] = w2[n * 64 + k];
    }
}

// ---------------- gather + concat: warp per group row ------------------------
__global__ void gather_k(const float* __restrict__ xyz, const float* __restrict__ feat) {
    int gw = (blockIdx.x * 256 + threadIdx.x) >> 5;   // row id 0..524287
    int lane = threadIdx.x & 31;
    int b = gw >> 16, s = (gw >> 5) & 2047;
    int j = g_gidx[gw];
    float* dst = g_X0 + (size_t)gw * 68;
    if (lane < 16) {
        ((float4*)dst)[lane] = ((const float4*)(feat + ((size_t)(b << 13) + j) * 64))[lane];
    } else if (lane == 16) {
        const float* xp = xyz + ((size_t)(b << 13) + j) * 3;
        const float* cp = g_cent + (b * 2048 + s) * 3;
        dst[64] = xp[0] - cp[0];
        dst[65] = xp[1] - cp[1];
        dst[66] = xp[2] - cp[2];
        dst[67] = 0.f;
    }
}

// ---------------- GEMM: 128-row tile, 256 thr, reg micro-tile ----------------
template<int KP, int N, bool ACT, bool STATS>
__global__ void __launch_bounds__(256) gemm_k(
    const float* __restrict__ A, const float* __restrict__ Wt,
    const float* __restrict__ bias,
    const float* __restrict__ fa, const float* __restrict__ fc,
    float* __restrict__ Y, float* __restrict__ gs, float* __restrict__ gq)
{
    extern __shared__ float sm[];
    float* As = sm;                  // [128][KP]
    float* Bs = sm + 128 * KP;       // [KP][N]
    float* Ss = Bs + KP * N;         // [2N] stats partials
    const int tid = threadIdx.x;
    const size_t rb = (size_t)blockIdx.x * 128;

    for (int i = tid; i < KP * N / 4; i += 256)
        ((float4*)Bs)[i] = ((const float4*)Wt)[i];
    if (STATS) for (int i = tid; i < 2 * N; i += 256) Ss[i] = 0.f;

    const int K4 = KP / 4;
    for (int i = tid; i < 128 * K4; i += 256) {
        int r = i / K4, c = i - r * K4;
        float4 v = ((const float4*)(A + (rb + r) * KP))[c];
        if (ACT) {
            int k = c * 4;
            v.x = fmaxf(fmaf(fa[k+0], v.x, fc[k+0]), 0.f);
            v.y = fmaxf(fmaf(fa[k+1], v.y, fc[k+1]), 0.f);
            v.z = fmaxf(fmaf(fa[k+2], v.z, fc[k+2]), 0.f);
            v.w = fmaxf(fmaf(fa[k+3], v.w, fc[k+3]), 0.f);
        }
        ((float4*)(As + r * KP))[c] = v;
    }
    __syncthreads();

    constexpr int NT = N / 16;                        // 4 or 8 cols/thread
    const int tc = (tid & 15) * NT, tr = tid >> 4;
    float acc[8][NT];
#pragma unroll
    for (int i = 0; i < 8; i++)
#pragma unroll
        for (int j = 0; j < NT; j++) acc[i][j] = bias[tc + j];

#pragma unroll 4
    for (int k = 0; k < KP; k++) {
        float av[8];
#pragma unroll
        for (int i = 0; i < 8; i++) av[i] = As[(tr + 16 * i) * KP + k];
        float bv[NT];
#pragma unroll
        for (int j = 0; j < NT; j += 4) {
            float4 t = *(const float4*)&Bs[k * N + tc + j];
            bv[j] = t.x; bv[j+1] = t.y; bv[j+2] = t.z; bv[j+3] = t.w;
        }
#pragma unroll
        for (int i = 0; i < 8; i++)
#pragma unroll
            for (int j = 0; j < NT; j++) acc[i][j] = fmaf(av[i], bv[j], acc[i][j]);
    }

#pragma unroll
    for (int i = 0; i < 8; i++) {
        size_t row = rb + tr + 16 * i;
#pragma unroll
        for (int j = 0; j < NT; j += 4) {
            float4 t = make_float4(acc[i][j], acc[i][j+1], acc[i][j+2], acc[i][j+3]);
            *(float4*)&Y[row * N + tc + j] = t;
        }
    }
    if (STATS) {
#pragma unroll
        for (int j = 0; j < NT; j++) {
            float s = 0.f, q = 0.f;
#pragma unroll
            for (int i = 0; i < 8; i++) { float v = acc[i][j]; s += v; q = fmaf(v, v, q); }
            atomicAdd(&Ss[tc + j], s);
            atomicAdd(&Ss[N + tc + j], q);
        }
        __syncthreads();
        for (int i = tid; i < N; i += 256) {
            atomicAdd(&gs[i], Ss[i]);
            atomicAdd(&gq[i], Ss[N + i]);
        }
    }
}

// ---------------- BN affine finalize -----------------------------------------
__global__ void finalize_k(const float* __restrict__ s, const float* __restrict__ q,
                           const float* __restrict__ g, const float* __restrict__ beta,
                           float* __restrict__ fa, float* __restrict__ fc, int n) {
    int i = blockIdx.x * 64 + threadIdx.x;
    if (i < n) {
        const float inv = 1.0f / 524288.0f;
        float m = s[i] * inv;
        float var = q[i] * inv - m * m;
        float a = g[i] * rsqrtf(var + 1e-5f);
        fa[i] = a;
        fc[i] = fmaf(-m, a, beta[i]);
    }
}

// ---------------- max over K + layer2 stats ----------------------------------
__global__ void __launch_bounds__(128) maxstat_k() {
    int g = blockIdx.x;                               // 0..16383
    int c = threadIdx.x;                              // 0..127
    const float* p = g_y2 + (size_t)g * 32 * 128 + c;
    float m = -3.4e38f, s = 0.f, q = 0.f;
#pragma unroll 4
    for (int r = 0; r < 32; r++) {
        float v = p[(size_t)r * 128];
        m = fmaxf(m, v);
        s += v;
        q = fmaf(v, v, q);
    }
    g_maxraw[g * 128 + c] = m;
    atomicAdd(&g_s2[c], s);
    atomicAdd(&g_q2[c], q);
}

// ---------------- final output ------------------------------------------------
__global__ void out_k(float* __restrict__ out) {
    int id = blockIdx.x * 256 + threadIdx.x;          // 0..2097151
    int c = id & 127;
    out[id] = fmaxf(fmaf(g_a2[c], g_maxraw[id], g_c2[c]), 0.f);
}

// ---------------- launch ------------------------------------------------------
extern "C" void kernel_launch(void* const* d_in, const int* in_sizes, int n_in,
                              void* d_out, int out_size) {
    const float* xyz  = (const float*)d_in[0];
    const float* feat = (const float*)d_in[1];
    const float* w0 = (const float*)d_in[2],  *b0 = (const float*)d_in[3];
    const float* g0 = (const float*)d_in[4],  *be0 = (const float*)d_in[5];
    const float* w1 = (const float*)d_in[6],  *b1 = (const float*)d_in[7];
    const float* g1 = (const float*)d_in[8],  *be1 = (const float*)d_in[9];
    const float* w2 = (const float*)d_in[10], *b2 = (const float*)d_in[11];
    const float* g2 = (const float*)d_in[12], *be2 = (const float*)d_in[13];
    float* out = (float*)d_out;

    float *ds0, *dq0, *ds1, *dq1, *ds2, *dq2;
    float *da0, *dc0, *da1, *dc1, *da2, *dc2;
    cudaGetSymbolAddress((void**)&ds0, g_s0); cudaGetSymbolAddress((void**)&dq0, g_q0);
    cudaGetSymbolAddress((void**)&ds1, g_s1); cudaGetSymbolAddress((void**)&dq1, g_q1);
    cudaGetSymbolAddress((void**)&ds2, g_s2); cudaGetSymbolAddress((void**)&dq2, g_q2);
    cudaGetSymbolAddress((void**)&da0, g_a0); cudaGetSymbolAddress((void**)&dc0, g_c0);
    cudaGetSymbolAddress((void**)&da1, g_a1); cudaGetSymbolAddress((void**)&dc1, g_c1);
    cudaGetSymbolAddress((void**)&da2, g_a2); cudaGetSymbolAddress((void**)&dc2, g_c2);
    float *dX0, *dy0, *dy1, *dy2, *dWt0, *dWt1, *dWt2;
    cudaGetSymbolAddress((void**)&dX0, g_X0);
    cudaGetSymbolAddress((void**)&dy0, g_y0);
    cudaGetSymbolAddress((void**)&dy1, g_y1);
    cudaGetSymbolAddress((void**)&dy2, g_y2);
    cudaGetSymbolAddress((void**)&dWt0, g_Wt0);
    cudaGetSymbolAddress((void**)&dWt1, g_Wt1);
    cudaGetSymbolAddress((void**)&dWt2, g_Wt2);

    const int smem0 = (128*68 + 68*64 + 128) * 4;
    const int smem1 = (128*64 + 64*64 + 128) * 4;
    const int smem2 = (128*64 + 64*128) * 4;
    cudaFuncSetAttribute(gemm_k<68,64,false,true>,  cudaFuncAttributeMaxDynamicSharedMemorySize, smem0);
    cudaFuncSetAttribute(gemm_k<64,64,true,true>,   cudaFuncAttributeMaxDynamicSharedMemorySize, smem1);
    cudaFuncSetAttribute(gemm_k<64,128,true,false>, cudaFuncAttributeMaxDynamicSharedMemorySize, smem2);

    zero_k<<<1, 128>>>();
    fps_k<<<8, 512>>>(xyz);
    centroid_k<<<64, 256>>>(xyz, out);                // out[0..49151] = centroids
    ballq_k<<<2048, 256>>>(xyz);
    prepw_k<<<65, 256>>>(w0, w1, w2);
    gather_k<<<65536, 256>>>(xyz, feat);
    gemm_k<68,64,false,true><<<4096, 256, smem0>>>(dX0, dWt0, b0, nullptr, nullptr, dy0, ds0, dq0);
    finalize_k<<<1, 64>>>(ds0, dq0, g0, be0, da0, dc0, 64);
    gemm_k<64,64,true,true><<<4096, 256, smem1>>>(dy0, dWt1, b1, da0, dc0, dy1, ds1, dq1);
    finalize_k<<<1, 64>>>(ds1, dq1, g1, be1, da1, dc1, 64);
    gemm_k<64,128,true,false><<<4096, 256, smem2>>>(dy1, dWt2, b2, da1, dc1, dy2, nullptr, nullptr);
    maxstat_k<<<16384, 128>>>();
    finalize_k<<<2, 64>>>(ds2, dq2, g2, be2, da2, dc2, 128);
    out_k<<<8192, 256>>>(out + 49152);
}